// round 5
// baseline (speedup 1.0000x reference)
#include <cuda_runtime.h>
#include <math.h>

#define FM_B 2
#define FM_C 256
#define FM_H 50
#define FM_W 50
#define FM_HW (FM_H * FM_W)      // 2500
#define POOL 7
#define NBINS (POOL * POOL)      // 49
#define R_ROIS 256

// Channel-last scratch: [B, H, W, C] = 2*50*50*256 floats = 5.12 MB
__device__ float d_fm_t[FM_B * FM_HW * FM_C];

// ---------------------------------------------------------------------------
// Kernel 1: transpose [B, C, HW] -> [B, HW, C] via 32x32 smem tiles
// ---------------------------------------------------------------------------
__global__ void transpose_kernel(const float* __restrict__ fm) {
    __shared__ float tile[32][33];
    int hw0 = blockIdx.x * 32;
    int c0  = blockIdx.y * 32;
    int b   = blockIdx.z;
    int tx = threadIdx.x;  // 0..31
    int ty = threadIdx.y;  // 0..7

    #pragma unroll
    for (int k = 0; k < 4; ++k) {
        int c  = c0 + ty + k * 8;
        int hw = hw0 + tx;
        if (hw < FM_HW)
            tile[ty + k * 8][tx] = fm[((size_t)b * FM_C + c) * FM_HW + hw];
    }
    __syncthreads();
    #pragma unroll
    for (int k = 0; k < 4; ++k) {
        int hw = hw0 + ty + k * 8;
        int c  = c0 + tx;
        if (hw < FM_HW)
            d_fm_t[((size_t)b * FM_HW + hw) * FM_C + c] = tile[tx][ty + k * 8];
    }
}

// ---------------------------------------------------------------------------
// Kernel 2: block = (roi, 32-channel group). lane = channel (coalesced loads).
// Each warp handles bins wid, wid+8, ... (all lanes share the window -> no
// divergence). Outputs staged in smem, written back coalesced.
// ---------------------------------------------------------------------------
__global__ void __launch_bounds__(256) roi_pool_kernel(
        const float* __restrict__ rois, float* __restrict__ out) {
    __shared__ int s_ws[POOL], s_we[POOL], s_hs[POOL], s_he[POOL];
    __shared__ int s_b;
    __shared__ float s_out[NBINS * 33];  // [bin][c_local], padded stride 33

    int r  = blockIdx.x >> 3;        // roi index
    int cg = blockIdx.x & 7;         // channel group (32 channels)
    int tid  = threadIdx.x;
    int wid  = tid >> 5;
    int lane = tid & 31;
    int c_local = lane;

    // Threads 0..6 compute bin edges (replicating XLA's x/7 -> x*fl(1/7))
    if (tid < POOL) {
        const float* roi = rois + r * 5;
        int b  = (int)roi[0];
        int x1 = (int)rintf(roi[1]);
        int y1 = (int)rintf(roi[2]);
        int x2 = (int)rintf(roi[3]);
        int y2 = (int)rintf(roi[4]);
        int roi_w = max(x2 - x1 + 1, 1);
        int roi_h = max(y2 - y1 + 1, 1);
        const float RCP7 = __uint_as_float(0x3E124925u);
        float bin_w = __fmul_rn((float)roi_w, RCP7);
        float bin_h = __fmul_rn((float)roi_h, RCP7);
        int p = tid;
        s_ws[p] = min(max(x1 + (int)floorf(__fmul_rn((float)p,       bin_w)), 0), FM_W);
        s_we[p] = min(max(x1 + (int)ceilf (__fmul_rn((float)(p + 1), bin_w)), 0), FM_W);
        s_hs[p] = min(max(y1 + (int)floorf(__fmul_rn((float)p,       bin_h)), 0), FM_H);
        s_he[p] = min(max(y1 + (int)ceilf (__fmul_rn((float)(p + 1), bin_h)), 0), FM_H);
        if (tid == 0) s_b = b;
    }
    __syncthreads();

    int b = s_b;
    const float* fmt = d_fm_t + ((size_t)b * FM_HW) * FM_C + cg * 32 + c_local;

    // Each warp handles bins wid, wid+8, ..., < 49
    for (int bin = wid; bin < NBINS; bin += 8) {
        int ph = bin / POOL;
        int pw = bin - ph * POOL;
        int ws = s_ws[pw], we = s_we[pw];
        int hs = s_hs[ph], he = s_he[ph];

        float m = -INFINITY;
        for (int h = hs; h < he; ++h) {
            const float* p = fmt + (size_t)(h * FM_W + ws) * FM_C;
            for (int w = ws; w < we; ++w) {
                m = fmaxf(m, __ldg(p));
                p += FM_C;
            }
        }
        s_out[bin * 33 + c_local] = isinf(m) ? 0.0f : m;
    }
    __syncthreads();

    // Coalesced store: out region for this block is contiguous
    // out[((r*256 + cg*32 + cl)*49) + bin], idx = cl*49 + bin in [0,1568)
    float* obase = out + (size_t)r * (FM_C * NBINS) + (size_t)cg * 32 * NBINS;
    #pragma unroll
    for (int i = 0; i < 7; ++i) {
        int idx = tid + i * 256;
        if (idx < 32 * NBINS) {
            int cl  = idx / NBINS;
            int bin = idx - cl * NBINS;
            obase[idx] = s_out[bin * 33 + cl];
        }
    }
}

extern "C" void kernel_launch(void* const* d_in, const int* in_sizes, int n_in,
                              void* d_out, int out_size) {
    const float* fm   = (const float*)d_in[0];
    const float* rois = (const float*)d_in[1];
    float* out        = (float*)d_out;

    dim3 tg((FM_HW + 31) / 32, FM_C / 32, FM_B);  // (79, 8, 2)
    transpose_kernel<<<tg, dim3(32, 8)>>>(fm);

    int blocks = R_ROIS * (FM_C / 32);  // 2048
    roi_pool_kernel<<<blocks, 256>>>(rois, out);
}

// round 6
// speedup vs baseline: 1.2619x; 1.2619x over previous
#include <cuda_runtime.h>
#include <math.h>

#define FM_B 2
#define FM_C 256
#define FM_H 50
#define FM_W 50
#define FM_HW (FM_H * FM_W)      // 2500
#define POOL 7
#define NBINS (POOL * POOL)      // 49
#define R_ROIS 256
#define C2 (FM_C / 2)            // position stride in float2 units (128)

// Channel-last scratch: [B, H, W, C] = 2*50*50*256 floats = 5.12 MB
__device__ float d_fm_t[FM_B * FM_HW * FM_C];

// ---------------------------------------------------------------------------
// Kernel 1: transpose [B, C, HW] -> [B, HW, C] via 32x32 smem tiles
// ---------------------------------------------------------------------------
__global__ void transpose_kernel(const float* __restrict__ fm) {
    __shared__ float tile[32][33];
    int hw0 = blockIdx.x * 32;
    int c0  = blockIdx.y * 32;
    int b   = blockIdx.z;
    int tx = threadIdx.x;
    int ty = threadIdx.y;

    #pragma unroll
    for (int k = 0; k < 4; ++k) {
        int c  = c0 + ty + k * 8;
        int hw = hw0 + tx;
        if (hw < FM_HW)
            tile[ty + k * 8][tx] = fm[((size_t)b * FM_C + c) * FM_HW + hw];
    }
    __syncthreads();
    #pragma unroll
    for (int k = 0; k < 4; ++k) {
        int hw = hw0 + ty + k * 8;
        int c  = c0 + tx;
        if (hw < FM_HW)
            d_fm_t[((size_t)b * FM_HW + hw) * FM_C + c] = tile[tx][ty + k * 8];
    }
}

// ---------------------------------------------------------------------------
// Kernel 2: block = (roi, 64-channel group). lane = 2 channels (float2).
// Warp handles bins wid, wid+8, ... All lanes share the bin window -> zero
// divergence. 2x2 (h,w) unroll with 4 independent accumulators -> MLP~4.
// ---------------------------------------------------------------------------
__global__ void __launch_bounds__(256) roi_pool_kernel(
        const float* __restrict__ rois, float* __restrict__ out) {
    __shared__ int s_ws[POOL], s_we[POOL], s_hs[POOL], s_he[POOL];
    __shared__ int s_b;
    __shared__ float s_out[NBINS * 65];  // [bin][c_local 0..63], pad 65

    int r  = blockIdx.x >> 2;        // roi index
    int cg = blockIdx.x & 3;         // 64-channel group
    int tid  = threadIdx.x;
    int wid  = tid >> 5;
    int lane = tid & 31;

    if (tid < POOL) {
        const float* roi = rois + r * 5;
        int b  = (int)roi[0];
        int x1 = (int)rintf(roi[1]);
        int y1 = (int)rintf(roi[2]);
        int x2 = (int)rintf(roi[3]);
        int y2 = (int)rintf(roi[4]);
        int roi_w = max(x2 - x1 + 1, 1);
        int roi_h = max(y2 - y1 + 1, 1);
        // Replicate XLA fast-math: x/7 -> x * fl(1/7)  (0x3E124925)
        const float RCP7 = __uint_as_float(0x3E124925u);
        float bin_w = __fmul_rn((float)roi_w, RCP7);
        float bin_h = __fmul_rn((float)roi_h, RCP7);
        int p = tid;
        s_ws[p] = min(max(x1 + (int)floorf(__fmul_rn((float)p,       bin_w)), 0), FM_W);
        s_we[p] = min(max(x1 + (int)ceilf (__fmul_rn((float)(p + 1), bin_w)), 0), FM_W);
        s_hs[p] = min(max(y1 + (int)floorf(__fmul_rn((float)p,       bin_h)), 0), FM_H);
        s_he[p] = min(max(y1 + (int)ceilf (__fmul_rn((float)(p + 1), bin_h)), 0), FM_H);
        if (tid == 0) s_b = (int)roi[0];
    }
    __syncthreads();

    int b = s_b;
    // lane's 2 channels: cg*64 + lane*2  -> float2 index cg*32 + lane
    const float2* fmt2 = reinterpret_cast<const float2*>(
        d_fm_t + (size_t)b * FM_HW * FM_C) + (size_t)cg * 32 + lane;

    const float2 NEG2 = make_float2(-INFINITY, -INFINITY);

    for (int bin = wid; bin < NBINS; bin += 8) {
        int ph = bin / POOL;
        int pw = bin - ph * POOL;
        int ws = s_ws[pw], we = s_we[pw];
        int hs = s_hs[ph], he = s_he[ph];

        float2 m0 = NEG2, m1 = NEG2, m2 = NEG2, m3 = NEG2;

        for (int h = hs; h < he; h += 2) {
            const float2* r0 = fmt2 + (size_t)(h * FM_W) * C2;
            const float2* r1 = r0 + FM_W * C2;
            bool h2 = (h + 1) < he;
            int w = ws;
            for (; w + 1 < we; w += 2) {
                float2 a = __ldg(r0 + (size_t)w * C2);
                float2 bv = __ldg(r0 + (size_t)(w + 1) * C2);
                float2 cv = NEG2, dv = NEG2;
                if (h2) cv = __ldg(r1 + (size_t)w * C2);
                if (h2) dv = __ldg(r1 + (size_t)(w + 1) * C2);
                m0.x = fmaxf(m0.x, a.x);  m0.y = fmaxf(m0.y, a.y);
                m1.x = fmaxf(m1.x, bv.x); m1.y = fmaxf(m1.y, bv.y);
                m2.x = fmaxf(m2.x, cv.x); m2.y = fmaxf(m2.y, cv.y);
                m3.x = fmaxf(m3.x, dv.x); m3.y = fmaxf(m3.y, dv.y);
            }
            if (w < we) {
                float2 a = __ldg(r0 + (size_t)w * C2);
                float2 cv = NEG2;
                if (h2) cv = __ldg(r1 + (size_t)w * C2);
                m0.x = fmaxf(m0.x, a.x);  m0.y = fmaxf(m0.y, a.y);
                m2.x = fmaxf(m2.x, cv.x); m2.y = fmaxf(m2.y, cv.y);
            }
        }
        float mx = fmaxf(fmaxf(m0.x, m1.x), fmaxf(m2.x, m3.x));
        float my = fmaxf(fmaxf(m0.y, m1.y), fmaxf(m2.y, m3.y));
        s_out[bin * 65 + lane * 2]     = isinf(mx) ? 0.0f : mx;
        s_out[bin * 65 + lane * 2 + 1] = isinf(my) ? 0.0f : my;
    }
    __syncthreads();

    // Coalesced store: this block's out region is contiguous:
    // out + r*(256*49) + cg*64*49, size 64*49 = 3136 floats.
    float* obase = out + (size_t)r * (FM_C * NBINS) + (size_t)cg * 64 * NBINS;
    #pragma unroll
    for (int i = 0; i < 13; ++i) {
        int idx = tid + i * 256;
        if (idx < 64 * NBINS) {
            int cl  = idx / NBINS;
            int bin = idx - cl * NBINS;
            obase[idx] = s_out[bin * 65 + cl];
        }
    }
}

extern "C" void kernel_launch(void* const* d_in, const int* in_sizes, int n_in,
                              void* d_out, int out_size) {
    const float* fm   = (const float*)d_in[0];
    const float* rois = (const float*)d_in[1];
    float* out        = (float*)d_out;

    dim3 tg((FM_HW + 31) / 32, FM_C / 32, FM_B);  // (79, 8, 2)
    transpose_kernel<<<tg, dim3(32, 8)>>>(fm);

    int blocks = R_ROIS * 4;  // 1024
    roi_pool_kernel<<<blocks, 256>>>(rois, out);
}